// round 16
// baseline (speedup 1.0000x reference)
#include <cuda_runtime.h>
#include <cuda_fp16.h>
#include <cstdint>

#define DM 512
#define NH 8
#define DK 64
#define BB 4
#define LL 2048
#define MROWS (BB*LL)                    // 8192
#define OUT_ELEMS ((size_t)MROWS*DM)     // 4,194,304
#define NROWS (BB*NH*LL)                 // 65536 softmax rows

__device__ __half g_Qh[MROWS*DM];   // Q * 0.125 in fp16
__device__ __half g_Kh[MROWS*DM];
__device__ __half g_Vh[MROWS*DM];
__device__ float g_rowinv[NROWS];

struct ProjArgs {
    const float* X[3];
    const float* W[3];
    const float* b[3];
    __half*      Y[3];
    float        scale[3];
};

#define LDMX4(R0,R1,R2,R3,addr) \
  asm volatile("ldmatrix.sync.aligned.m8n8.x4.shared.b16 {%0,%1,%2,%3}, [%4];" \
    : "=r"(R0),"=r"(R1),"=r"(R2),"=r"(R3) : "r"(addr))
#define LDMX4T(R0,R1,R2,R3,addr) \
  asm volatile("ldmatrix.sync.aligned.m8n8.x4.trans.shared.b16 {%0,%1,%2,%3}, [%4];" \
    : "=r"(R0),"=r"(R1),"=r"(R2),"=r"(R3) : "r"(addr))
#define MMA16816(C, A0,A1,A2,A3, B0,B1) \
  asm volatile("mma.sync.aligned.m16n8k16.row.col.f32.f16.f16.f32 " \
    "{%0,%1,%2,%3}, {%4,%5,%6,%7}, {%8,%9}, {%0,%1,%2,%3};" \
    : "+f"(C[0]),"+f"(C[1]),"+f"(C[2]),"+f"(C[3]) \
    : "r"(A0),"r"(A1),"r"(A2),"r"(A3), "r"(B0),"r"(B1))
#define CP_ASYNC16(dst, src) \
  asm volatile("cp.async.cg.shared.global [%0], [%1], 16;" :: "r"(dst), "l"(src))
#define CP_COMMIT() asm volatile("cp.async.commit_group;")
#define CP_WAIT0()  asm volatile("cp.async.wait_group 0;")

__device__ __forceinline__ unsigned int smem_u32(const void* p) {
    return (unsigned int)__cvta_generic_to_shared(p);
}

// ---------------------------------------------------------------------------
// Fused projections via HMMA, register-prefetch pipelined: gmem loads of
// chunk k+1 issue BEFORE the MMA of chunk k.  grid (4, 64, 3), 256 threads.
// ---------------------------------------------------------------------------
__global__ void __launch_bounds__(256) proj_tc_kernel(ProjArgs args)
{
    const int z = blockIdx.z;
    const float* __restrict__ X    = args.X[z];
    const float* __restrict__ W    = args.W[z];
    const float* __restrict__ bias = args.b[z];
    __half* __restrict__ Y         = args.Y[z];
    const float qs                 = args.scale[z];

    __shared__ uint4 Xs[128*5];
    __shared__ uint4 Ws[32*16];

    const int tid = threadIdx.x;
    const int lane = tid & 31, w = tid >> 5;
    const int bm = blockIdx.y * 128, bn = blockIdx.x * 128;
    const int wm = (w & 3) * 32, wn = (w >> 2) * 64;

    const unsigned int xbase = smem_u32(Xs), wbase = smem_u32(Ws);

    const int xr = tid >> 1;
    const int xc2 = (tid & 1) * 2;
    const int wr = tid >> 3;
    const int wc2 = (tid & 7) * 2;

    float acc[2][8][4] = {};

    float4 xa, xb, xc, xd, wa, wb, wc, wd;
    // prologue: load chunk 0
    {
        const float* Xp = &X[(size_t)(bm + xr) * 512 + xc2*8];
        const float* Wp = &W[(size_t)wr * 512 + bn + wc2*8];
        xa = *(const float4*)&Xp[0];  xb = *(const float4*)&Xp[4];
        xc = *(const float4*)&Xp[8];  xd = *(const float4*)&Xp[12];
        wa = *(const float4*)&Wp[0];  wb = *(const float4*)&Wp[4];
        wc = *(const float4*)&Wp[8];  wd = *(const float4*)&Wp[12];
    }

    for (int k0 = 0; k0 < 512; k0 += 32) {
        __syncthreads();   // previous MMA done reading smem
        {
            __half2 h0 = __floats2half2_rn(xa.x, xa.y), h1 = __floats2half2_rn(xa.z, xa.w);
            __half2 h2 = __floats2half2_rn(xb.x, xb.y), h3 = __floats2half2_rn(xb.z, xb.w);
            uint4 p0; p0.x = *(unsigned int*)&h0; p0.y = *(unsigned int*)&h1;
                      p0.z = *(unsigned int*)&h2; p0.w = *(unsigned int*)&h3;
            __half2 h4 = __floats2half2_rn(xc.x, xc.y), h5 = __floats2half2_rn(xc.z, xc.w);
            __half2 h6 = __floats2half2_rn(xd.x, xd.y), h7 = __floats2half2_rn(xd.z, xd.w);
            uint4 p1; p1.x = *(unsigned int*)&h4; p1.y = *(unsigned int*)&h5;
                      p1.z = *(unsigned int*)&h6; p1.w = *(unsigned int*)&h7;
            Xs[xr*5 + xc2]     = p0;
            Xs[xr*5 + xc2 + 1] = p1;
        }
        {
            __half2 h0 = __floats2half2_rn(wa.x, wa.y), h1 = __floats2half2_rn(wa.z, wa.w);
            __half2 h2 = __floats2half2_rn(wb.x, wb.y), h3 = __floats2half2_rn(wb.z, wb.w);
            uint4 p0; p0.x = *(unsigned int*)&h0; p0.y = *(unsigned int*)&h1;
                      p0.z = *(unsigned int*)&h2; p0.w = *(unsigned int*)&h3;
            __half2 h4 = __floats2half2_rn(wc.x, wc.y), h5 = __floats2half2_rn(wc.z, wc.w);
            __half2 h6 = __floats2half2_rn(wd.x, wd.y), h7 = __floats2half2_rn(wd.z, wd.w);
            uint4 p1; p1.x = *(unsigned int*)&h4; p1.y = *(unsigned int*)&h5;
                      p1.z = *(unsigned int*)&h6; p1.w = *(unsigned int*)&h7;
            Ws[wr*16 + ((wc2)     ^ (wr & 7))] = p0;
            Ws[wr*16 + ((wc2 + 1) ^ (wr & 7))] = p1;
        }
        __syncthreads();

        // prefetch chunk k+1 (overlaps the MMA below)
        if (k0 + 32 < 512) {
            const float* Xp = &X[(size_t)(bm + xr) * 512 + (k0 + 32) + xc2*8];
            const float* Wp = &W[(size_t)(k0 + 32 + wr) * 512 + bn + wc2*8];
            xa = *(const float4*)&Xp[0];  xb = *(const float4*)&Xp[4];
            xc = *(const float4*)&Xp[8];  xd = *(const float4*)&Xp[12];
            wa = *(const float4*)&Wp[0];  wb = *(const float4*)&Wp[4];
            wc = *(const float4*)&Wp[8];  wd = *(const float4*)&Wp[12];
        }

        #pragma unroll
        for (int ks = 0; ks < 2; ks++) {
            unsigned int a[2][4];
            #pragma unroll
            for (int t = 0; t < 2; t++) {
                int r = wm + t*16 + (lane & 15);
                int c = ks*2 + (lane >> 4);
                LDMX4(a[t][0], a[t][1], a[t][2], a[t][3], xbase + (r*5 + c)*16);
            }
            #pragma unroll
            for (int u2 = 0; u2 < 4; u2++) {
                unsigned int bf[4];
                int r = ks*16 + (lane & 7) + (((lane >> 3) & 1) << 3);
                int c = ((wn >> 3) + u2*2 + ((lane >> 4) & 1)) ^ (r & 7);
                LDMX4T(bf[0], bf[1], bf[2], bf[3], wbase + (r*16 + c)*16);
                #pragma unroll
                for (int t = 0; t < 2; t++) {
                    MMA16816(acc[t][u2*2],   a[t][0],a[t][1],a[t][2],a[t][3], bf[0], bf[1]);
                    MMA16816(acc[t][u2*2+1], a[t][0],a[t][1],a[t][2],a[t][3], bf[2], bf[3]);
                }
            }
        }
    }

    #pragma unroll
    for (int t = 0; t < 2; t++) {
        #pragma unroll
        for (int u = 0; u < 8; u++) {
            int c = bn + wn + u*8 + (lane & 3)*2;
            float2 bv = *(const float2*)&bias[c];
            #pragma unroll
            for (int hh = 0; hh < 2; hh++) {
                int r = bm + wm + t*16 + (lane >> 2) + hh*8;
                __half2 o = __floats2half2_rn((acc[t][u][hh*2]   + bv.x) * qs,
                                              (acc[t][u][hh*2+1] + bv.y) * qs);
                *(unsigned int*)&Y[(size_t)r * 512 + c] = *(unsigned int*)&o;
            }
        }
    }
}

// ---------------------------------------------------------------------------
// Stats v2: persistent-Q row-sum pass (unchanged from round 15).
// ---------------------------------------------------------------------------
__global__ void __launch_bounds__(128) stats_tc_kernel()
{
    __shared__ uint4 Qs[128*8];      // 16KB
    __shared__ uint4 Ks[2][64*8];    // 16KB

    const int tid = threadIdx.x;
    const int lane = tid & 31, w = tid >> 5;       // 4 warps
    const int bh = blockIdx.y, b = bh >> 3, h = bh & 7;
    const int bm = blockIdx.x * 128;
    const __half* __restrict__ Qg = g_Qh + (size_t)b * LL * DM + h * DK;
    const __half* __restrict__ Kg = g_Kh + (size_t)b * LL * DM + h * DK;

    const unsigned int qbase = smem_u32(Qs);
    const unsigned int kbase = smem_u32(Ks);

    for (int ci = tid; ci < 1024; ci += 128) {
        int r = ci >> 3, c = ci & 7;
        Qs[r*8 + (c ^ (r & 7))] = *(const uint4*)&Qg[(size_t)(bm + r) * DM + c*8];
    }
    #pragma unroll
    for (int ci = tid; ci < 512; ci += 128) {
        int r = ci >> 3, c = ci & 7;
        CP_ASYNC16(kbase + (r*8 + (c ^ (r & 7)))*16, &Kg[(size_t)r * DM + c*8]);
    }
    CP_COMMIT();
    __syncthreads();

    const int wm = w * 32;
    unsigned int qf[2][4][4];
    #pragma unroll
    for (int mt = 0; mt < 2; mt++) {
        #pragma unroll
        for (int ks = 0; ks < 4; ks++) {
            int r = wm + mt*16 + (lane & 15);
            int c = (ks*2 + (lane >> 4)) ^ (r & 7);
            LDMX4(qf[mt][ks][0], qf[mt][ks][1], qf[mt][ks][2], qf[mt][ks][3],
                  qbase + (r*8 + c)*16);
        }
    }

    float rsum[2][2] = {};

    for (int kc = 0; kc < LL; kc += 64) {
        const int buf = (kc >> 6) & 1;
        CP_WAIT0();
        __syncthreads();
        if (kc + 64 < LL) {
            const unsigned int koff = kbase + (buf ^ 1) * (512*16);
            #pragma unroll
            for (int ci = tid; ci < 512; ci += 128) {
                int r = ci >> 3, c = ci & 7;
                CP_ASYNC16(koff + (r*8 + (c ^ (r & 7)))*16,
                           &Kg[(size_t)(kc + 64 + r) * DM + c*8]);
            }
            CP_COMMIT();
        }

        const unsigned int kb = kbase + buf * (512*16);
        #pragma unroll
        for (int u2 = 0; u2 < 4; u2++) {
            float sacc[2][2][4] = {};
            #pragma unroll
            for (int ks = 0; ks < 4; ks++) {
                unsigned int bf[4];
                int r = u2*16 + (lane & 7) + ((lane >> 4) << 3);
                int c = (ks*2 + ((lane >> 3) & 1)) ^ (r & 7);
                LDMX4(bf[0], bf[1], bf[2], bf[3], kb + (r*8 + c)*16);
                #pragma unroll
                for (int mt = 0; mt < 2; mt++) {
                    MMA16816(sacc[mt][0], qf[mt][ks][0],qf[mt][ks][1],qf[mt][ks][2],qf[mt][ks][3], bf[0], bf[1]);
                    MMA16816(sacc[mt][1], qf[mt][ks][0],qf[mt][ks][1],qf[mt][ks][2],qf[mt][ks][3], bf[2], bf[3]);
                }
            }
            #pragma unroll
            for (int mt = 0; mt < 2; mt++) {
                #pragma unroll
                for (int j = 0; j < 2; j++) {
                    rsum[mt][0] += __expf(sacc[mt][j][0]) + __expf(sacc[mt][j][1]);
                    rsum[mt][1] += __expf(sacc[mt][j][2]) + __expf(sacc[mt][j][3]);
                }
            }
        }
        __syncthreads();
    }

    const int lrow = lane >> 2;
    #pragma unroll
    for (int mt = 0; mt < 2; mt++) {
        #pragma unroll
        for (int hh = 0; hh < 2; hh++) {
            float s = rsum[mt][hh];
            s += __shfl_xor_sync(0xffffffffu, s, 1);
            s += __shfl_xor_sync(0xffffffffu, s, 2);
            if ((lane & 3) == 0)
                g_rowinv[bh * LL + bm + wm + mt*16 + lrow + hh*8] = 1.0f / s;
        }
    }
}

// ---------------------------------------------------------------------------
// Fused P + O pass (unchanged from round 14).
// ---------------------------------------------------------------------------
__global__ void __launch_bounds__(128) fused_pav_kernel(float* __restrict__ attn,
                                                        float* __restrict__ out)
{
    __shared__ uint4 Qs[128*8];      // 16KB
    __shared__ uint4 Ks[2][64*8];    // 16KB
    __shared__ uint4 Vs[2][64*8];    // 16KB

    const int tid = threadIdx.x;
    const int lane = tid & 31, w = tid >> 5;       // 4 warps
    const int bh = blockIdx.y, b = bh >> 3, h = bh & 7;
    const int bm = blockIdx.x * 128;
    float* __restrict__ P = attn + (size_t)bh * LL * LL;
    const __half* __restrict__ Qg = g_Qh + (size_t)b * LL * DM + h * DK;
    const __half* __restrict__ Kg = g_Kh + (size_t)b * LL * DM + h * DK;
    const __half* __restrict__ Vg = g_Vh + (size_t)b * LL * DM + h * DK;

    const unsigned int qbase = smem_u32(Qs);
    const unsigned int kbase = smem_u32(Ks);
    const unsigned int vbase = smem_u32(Vs);

    for (int ci = tid; ci < 1024; ci += 128) {
        int r = ci >> 3, c = ci & 7;
        Qs[r*8 + (c ^ (r & 7))] = *(const uint4*)&Qg[(size_t)(bm + r) * DM + c*8];
    }
    #pragma unroll
    for (int ci = tid; ci < 512; ci += 128) {
        int r = ci >> 3, c = ci & 7;
        unsigned int off = (r*8 + (c ^ (r & 7)))*16;
        CP_ASYNC16(kbase + off, &Kg[(size_t)r * DM + c*8]);
        CP_ASYNC16(vbase + off, &Vg[(size_t)r * DM + c*8]);
    }
    CP_COMMIT();
    __syncthreads();

    const int wm = w * 32;
    unsigned int qf[2][4][4];
    #pragma unroll
    for (int mt = 0; mt < 2; mt++) {
        #pragma unroll
        for (int ks = 0; ks < 4; ks++) {
            int r = wm + mt*16 + (lane & 15);
            int c = (ks*2 + (lane >> 4)) ^ (r & 7);
            LDMX4(qf[mt][ks][0], qf[mt][ks][1], qf[mt][ks][2], qf[mt][ks][3],
                  qbase + (r*8 + c)*16);
        }
    }

    const int lrow = lane >> 2;
    float inv[2][2];
    #pragma unroll
    for (int mt = 0; mt < 2; mt++) {
        inv[mt][0] = g_rowinv[bh * LL + bm + wm + mt*16 + lrow];
        inv[mt][1] = g_rowinv[bh * LL + bm + wm + mt*16 + lrow + 8];
    }
    const int cl2 = (lane & 3) * 2;

    float oacc[2][8][4] = {};

    for (int kc = 0; kc < LL; kc += 64) {
        const int buf = (kc >> 6) & 1;
        CP_WAIT0();
        __syncthreads();
        if (kc + 64 < LL) {
            const unsigned int koff = kbase + (buf ^ 1) * (512*16);
            const unsigned int voff = vbase + (buf ^ 1) * (512*16);
            #pragma unroll
            for (int ci = tid; ci < 512; ci += 128) {
                int r = ci >> 3, c = ci & 7;
                unsigned int off = (r*8 + (c ^ (r & 7)))*16;
                CP_ASYNC16(koff + off, &Kg[(size_t)(kc + 64 + r) * DM + c*8]);
                CP_ASYNC16(voff + off, &Vg[(size_t)(kc + 64 + r) * DM + c*8]);
            }
            CP_COMMIT();
        }

        const unsigned int kb = kbase + buf * (512*16);
        unsigned int afr[2][4][4];
        #pragma unroll
        for (int u2 = 0; u2 < 4; u2++) {
            float sacc[2][2][4] = {};
            #pragma unroll
            for (int ks = 0; ks < 4; ks++) {
                unsigned int bf[4];
                int r = u2*16 + (lane & 7) + ((lane >> 4) << 3);
                int c = (ks*2 + ((lane >> 3) & 1)) ^ (r & 7);
                LDMX4(bf[0], bf[1], bf[2], bf[3], kb + (r*8 + c)*16);
                #pragma unroll
                for (int mt = 0; mt < 2; mt++) {
                    MMA16816(sacc[mt][0], qf[mt][ks][0],qf[mt][ks][1],qf[mt][ks][2],qf[mt][ks][3], bf[0], bf[1]);
                    MMA16816(sacc[mt][1], qf[mt][ks][0],qf[mt][ks][1],qf[mt][ks][2],qf[mt][ks][3], bf[2], bf[3]);
                }
            }
            #pragma unroll
            for (int mt = 0; mt < 2; mt++) {
                #pragma unroll
                for (int j = 0; j < 2; j++) {
                    float2 p0, p1;
                    p0.x = __expf(sacc[mt][j][0]) * inv[mt][0];
                    p0.y = __expf(sacc[mt][j][1]) * inv[mt][0];
                    p1.x = __expf(sacc[mt][j][2]) * inv[mt][1];
                    p1.y = __expf(sacc[mt][j][3]) * inv[mt][1];
                    int rowa = bm + wm + mt*16 + lrow;
                    int col  = kc + u2*16 + j*8 + cl2;
                    *(float2*)&P[(size_t)rowa * LL + col]       = p0;
                    *(float2*)&P[(size_t)(rowa + 8) * LL + col] = p1;
                    __half2 h0 = __floats2half2_rn(p0.x, p0.y);
                    __half2 h1 = __floats2half2_rn(p1.x, p1.y);
                    afr[mt][u2][j*2 + 0] = *(unsigned int*)&h0;
                    afr[mt][u2][j*2 + 1] = *(unsigned int*)&h1;
                }
            }
        }

        const unsigned int vb = vbase + buf * (512*16);
        #pragma unroll
        for (int kk = 0; kk < 4; kk++) {
            #pragma unroll
            for (int u2 = 0; u2 < 4; u2++) {
                unsigned int bf[4];
                int r = kk*16 + (lane & 7) + (((lane >> 3) & 1) << 3);
                int c = (u2*2 + ((lane >> 4) & 1)) ^ (r & 7);
                LDMX4T(bf[0], bf[1], bf[2], bf[3], vb + (r*8 + c)*16);
                #pragma unroll
                for (int mt = 0; mt < 2; mt++) {
                    MMA16816(oacc[mt][u2*2],   afr[mt][kk][0],afr[mt][kk][1],afr[mt][kk][2],afr[mt][kk][3], bf[0], bf[1]);
                    MMA16816(oacc[mt][u2*2+1], afr[mt][kk][0],afr[mt][kk][1],afr[mt][kk][2],afr[mt][kk][3], bf[2], bf[3]);
                }
            }
        }
        __syncthreads();
    }

    #pragma unroll
    for (int mt = 0; mt < 2; mt++) {
        #pragma unroll
        for (int u = 0; u < 8; u++) {
            #pragma unroll
            for (int hh = 0; hh < 2; hh++) {
                int r = bm + wm + mt*16 + lrow + hh*8;
                float2 v = make_float2(oacc[mt][u][hh*2], oacc[mt][u][hh*2+1]);
                *(float2*)&out[(size_t)(b * LL + r) * DM + h * DK + u*8 + cl2] = v;
            }
        }
    }
}

// ---------------------------------------------------------------------------
extern "C" void kernel_launch(void* const* d_in, const int* in_sizes, int n_in,
                              void* d_out, int out_size)
{
    const float* q  = (const float*)d_in[0];
    const float* k  = (const float*)d_in[1];
    const float* v  = (const float*)d_in[2];
    const float* Wq = (const float*)d_in[3];
    const float* bq = (const float*)d_in[4];
    const float* Wk = (const float*)d_in[5];
    const float* bk = (const float*)d_in[6];
    const float* Wv = (const float*)d_in[7];
    const float* bv = (const float*)d_in[8];

    float* out  = (float*)d_out;
    float* attn = out + OUT_ELEMS;

    __half *gQ, *gK, *gV;
    cudaGetSymbolAddress((void**)&gQ, g_Qh);
    cudaGetSymbolAddress((void**)&gK, g_Kh);
    cudaGetSymbolAddress((void**)&gV, g_Vh);

    ProjArgs pa;
    pa.X[0] = q;  pa.X[1] = k;  pa.X[2] = v;
    pa.W[0] = Wq; pa.W[1] = Wk; pa.W[2] = Wv;
    pa.b[0] = bq; pa.b[1] = bk; pa.b[2] = bv;
    pa.Y[0] = gQ; pa.Y[1] = gK; pa.Y[2] = gV;
    pa.scale[0] = 0.125f; pa.scale[1] = 1.0f; pa.scale[2] = 1.0f;

    proj_tc_kernel<<<dim3(4, 64, 3), dim3(256)>>>(pa);
    stats_tc_kernel<<<dim3(16, 32), dim3(128)>>>();
    fused_pav_kernel<<<dim3(16, 32), dim3(128)>>>(attn, out);
}

// round 17
// speedup vs baseline: 1.1101x; 1.1101x over previous
#include <cuda_runtime.h>
#include <cuda_fp16.h>
#include <cstdint>

#define DM 512
#define NH 8
#define DK 64
#define BB 4
#define LL 2048
#define MROWS (BB*LL)                    // 8192
#define OUT_ELEMS ((size_t)MROWS*DM)     // 4,194,304

__device__ __half g_Qh[MROWS*DM];   // Q * 0.125 in fp16
__device__ __half g_Kh[MROWS*DM];
__device__ __half g_Vh[MROWS*DM];

struct ProjArgs {
    const float* X[3];
    const float* W[3];
    const float* b[3];
    __half*      Y[3];
    float        scale[3];
};

#define LDMX4(R0,R1,R2,R3,addr) \
  asm volatile("ldmatrix.sync.aligned.m8n8.x4.shared.b16 {%0,%1,%2,%3}, [%4];" \
    : "=r"(R0),"=r"(R1),"=r"(R2),"=r"(R3) : "r"(addr))
#define LDMX4T(R0,R1,R2,R3,addr) \
  asm volatile("ldmatrix.sync.aligned.m8n8.x4.trans.shared.b16 {%0,%1,%2,%3}, [%4];" \
    : "=r"(R0),"=r"(R1),"=r"(R2),"=r"(R3) : "r"(addr))
#define MMA16816(C, A0,A1,A2,A3, B0,B1) \
  asm volatile("mma.sync.aligned.m16n8k16.row.col.f32.f16.f16.f32 " \
    "{%0,%1,%2,%3}, {%4,%5,%6,%7}, {%8,%9}, {%0,%1,%2,%3};" \
    : "+f"(C[0]),"+f"(C[1]),"+f"(C[2]),"+f"(C[3]) \
    : "r"(A0),"r"(A1),"r"(A2),"r"(A3), "r"(B0),"r"(B1))
#define CP_ASYNC16(dst, src) \
  asm volatile("cp.async.cg.shared.global [%0], [%1], 16;" :: "r"(dst), "l"(src))
#define CP_COMMIT() asm volatile("cp.async.commit_group;")
#define CP_WAIT0()  asm volatile("cp.async.wait_group 0;")

__device__ __forceinline__ unsigned int smem_u32(const void* p) {
    return (unsigned int)__cvta_generic_to_shared(p);
}

// ---------------------------------------------------------------------------
// Fused projections via HMMA (round-15 version: loads at loop top, no reg
// prefetch — occupancy-friendly).  grid (4, 64, 3), 256 threads.
// ---------------------------------------------------------------------------
__global__ void __launch_bounds__(256) proj_tc_kernel(ProjArgs args)
{
    const int z = blockIdx.z;
    const float* __restrict__ X    = args.X[z];
    const float* __restrict__ W    = args.W[z];
    const float* __restrict__ bias = args.b[z];
    __half* __restrict__ Y         = args.Y[z];
    const float qs                 = args.scale[z];

    __shared__ uint4 Xs[128*5];
    __shared__ uint4 Ws[32*16];

    const int tid = threadIdx.x;
    const int lane = tid & 31, w = tid >> 5;
    const int bm = blockIdx.y * 128, bn = blockIdx.x * 128;
    const int wm = (w & 3) * 32, wn = (w >> 2) * 64;

    const unsigned int xbase = smem_u32(Xs), wbase = smem_u32(Ws);

    const int xr = tid >> 1;
    const int xc2 = (tid & 1) * 2;
    const int wr = tid >> 3;
    const int wc2 = (tid & 7) * 2;

    float acc[2][8][4] = {};

    for (int k0 = 0; k0 < 512; k0 += 32) {
        float4 xa = *(const float4*)&X[(size_t)(bm + xr) * 512 + k0 + xc2*8];
        float4 xb = *(const float4*)&X[(size_t)(bm + xr) * 512 + k0 + xc2*8 + 4];
        float4 xc = *(const float4*)&X[(size_t)(bm + xr) * 512 + k0 + xc2*8 + 8];
        float4 xd = *(const float4*)&X[(size_t)(bm + xr) * 512 + k0 + xc2*8 + 12];
        float4 wa = *(const float4*)&W[(size_t)(k0 + wr) * 512 + bn + wc2*8];
        float4 wb = *(const float4*)&W[(size_t)(k0 + wr) * 512 + bn + wc2*8 + 4];
        float4 wc = *(const float4*)&W[(size_t)(k0 + wr) * 512 + bn + wc2*8 + 8];
        float4 wd = *(const float4*)&W[(size_t)(k0 + wr) * 512 + bn + wc2*8 + 12];
        __syncthreads();
        {
            __half2 h0 = __floats2half2_rn(xa.x, xa.y), h1 = __floats2half2_rn(xa.z, xa.w);
            __half2 h2 = __floats2half2_rn(xb.x, xb.y), h3 = __floats2half2_rn(xb.z, xb.w);
            uint4 p0; p0.x = *(unsigned int*)&h0; p0.y = *(unsigned int*)&h1;
                      p0.z = *(unsigned int*)&h2; p0.w = *(unsigned int*)&h3;
            __half2 h4 = __floats2half2_rn(xc.x, xc.y), h5 = __floats2half2_rn(xc.z, xc.w);
            __half2 h6 = __floats2half2_rn(xd.x, xd.y), h7 = __floats2half2_rn(xd.z, xd.w);
            uint4 p1; p1.x = *(unsigned int*)&h4; p1.y = *(unsigned int*)&h5;
                      p1.z = *(unsigned int*)&h6; p1.w = *(unsigned int*)&h7;
            Xs[xr*5 + xc2]     = p0;
            Xs[xr*5 + xc2 + 1] = p1;
        }
        {
            __half2 h0 = __floats2half2_rn(wa.x, wa.y), h1 = __floats2half2_rn(wa.z, wa.w);
            __half2 h2 = __floats2half2_rn(wb.x, wb.y), h3 = __floats2half2_rn(wb.z, wb.w);
            uint4 p0; p0.x = *(unsigned int*)&h0; p0.y = *(unsigned int*)&h1;
                      p0.z = *(unsigned int*)&h2; p0.w = *(unsigned int*)&h3;
            __half2 h4 = __floats2half2_rn(wc.x, wc.y), h5 = __floats2half2_rn(wc.z, wc.w);
            __half2 h6 = __floats2half2_rn(wd.x, wd.y), h7 = __floats2half2_rn(wd.z, wd.w);
            uint4 p1; p1.x = *(unsigned int*)&h4; p1.y = *(unsigned int*)&h5;
                      p1.z = *(unsigned int*)&h6; p1.w = *(unsigned int*)&h7;
            Ws[wr*16 + ((wc2)     ^ (wr & 7))] = p0;
            Ws[wr*16 + ((wc2 + 1) ^ (wr & 7))] = p1;
        }
        __syncthreads();

        #pragma unroll
        for (int ks = 0; ks < 2; ks++) {
            unsigned int a[2][4];
            #pragma unroll
            for (int t = 0; t < 2; t++) {
                int r = wm + t*16 + (lane & 15);
                int c = ks*2 + (lane >> 4);
                LDMX4(a[t][0], a[t][1], a[t][2], a[t][3], xbase + (r*5 + c)*16);
            }
            #pragma unroll
            for (int u2 = 0; u2 < 4; u2++) {
                unsigned int bf[4];
                int r = ks*16 + (lane & 7) + (((lane >> 3) & 1) << 3);
                int c = ((wn >> 3) + u2*2 + ((lane >> 4) & 1)) ^ (r & 7);
                LDMX4T(bf[0], bf[1], bf[2], bf[3], wbase + (r*16 + c)*16);
                #pragma unroll
                for (int t = 0; t < 2; t++) {
                    MMA16816(acc[t][u2*2],   a[t][0],a[t][1],a[t][2],a[t][3], bf[0], bf[1]);
                    MMA16816(acc[t][u2*2+1], a[t][0],a[t][1],a[t][2],a[t][3], bf[2], bf[3]);
                }
            }
        }
    }

    #pragma unroll
    for (int t = 0; t < 2; t++) {
        #pragma unroll
        for (int u = 0; u < 8; u++) {
            int c = bn + wn + u*8 + (lane & 3)*2;
            float2 bv = *(const float2*)&bias[c];
            #pragma unroll
            for (int hh = 0; hh < 2; hh++) {
                int r = bm + wm + t*16 + (lane >> 2) + hh*8;
                __half2 o = __floats2half2_rn((acc[t][u][hh*2]   + bv.x) * qs,
                                              (acc[t][u][hh*2+1] + bv.y) * qs);
                *(unsigned int*)&Y[(size_t)r * 512 + c] = *(unsigned int*)&o;
            }
        }
    }
}

// ---------------------------------------------------------------------------
// Merged attention kernel: phase 1 computes per-row 1/sum(exp(S)) with K-only
// cp.async pipeline (inv kept in registers — shfl reduce leaves full sum in
// all 4 quad lanes); phase 2 recomputes S, writes P once, accumulates O.
// grid (16, 32), 128 threads = 4 warps x 32 rows.
// ---------------------------------------------------------------------------
__global__ void __launch_bounds__(128) attn_fused_kernel(float* __restrict__ attn,
                                                         float* __restrict__ out)
{
    __shared__ uint4 Qs[128*8];      // 16KB
    __shared__ uint4 Ks[2][64*8];    // 16KB
    __shared__ uint4 Vs[2][64*8];    // 16KB

    const int tid = threadIdx.x;
    const int lane = tid & 31, w = tid >> 5;       // 4 warps
    const int bh = blockIdx.y, b = bh >> 3, h = bh & 7;
    const int bm = blockIdx.x * 128;
    float* __restrict__ P = attn + (size_t)bh * LL * LL;
    const __half* __restrict__ Qg = g_Qh + (size_t)b * LL * DM + h * DK;
    const __half* __restrict__ Kg = g_Kh + (size_t)b * LL * DM + h * DK;
    const __half* __restrict__ Vg = g_Vh + (size_t)b * LL * DM + h * DK;

    const unsigned int qbase = smem_u32(Qs);
    const unsigned int kbase = smem_u32(Ks);
    const unsigned int vbase = smem_u32(Vs);

    // Q tile 128x64 -> smem, cp.async K chunk 0
    for (int ci = tid; ci < 1024; ci += 128) {
        int r = ci >> 3, c = ci & 7;
        Qs[r*8 + (c ^ (r & 7))] = *(const uint4*)&Qg[(size_t)(bm + r) * DM + c*8];
    }
    #pragma unroll
    for (int ci = tid; ci < 512; ci += 128) {
        int r = ci >> 3, c = ci & 7;
        CP_ASYNC16(kbase + (r*8 + (c ^ (r & 7)))*16, &Kg[(size_t)r * DM + c*8]);
    }
    CP_COMMIT();
    __syncthreads();

    // Q fragments (persist across both phases)
    const int wm = w * 32;
    unsigned int qf[2][4][4];
    #pragma unroll
    for (int mt = 0; mt < 2; mt++) {
        #pragma unroll
        for (int ks = 0; ks < 4; ks++) {
            int r = wm + mt*16 + (lane & 15);
            int c = (ks*2 + (lane >> 4)) ^ (r & 7);
            LDMX4(qf[mt][ks][0], qf[mt][ks][1], qf[mt][ks][2], qf[mt][ks][3],
                  qbase + (r*8 + c)*16);
        }
    }

    // ---------------- Phase 1: row sums ----------------
    float rsum[2][2] = {};

    for (int kc = 0; kc < LL; kc += 64) {
        const int buf = (kc >> 6) & 1;
        CP_WAIT0();
        __syncthreads();
        if (kc + 64 < LL) {
            const unsigned int koff = kbase + (buf ^ 1) * (512*16);
            #pragma unroll
            for (int ci = tid; ci < 512; ci += 128) {
                int r = ci >> 3, c = ci & 7;
                CP_ASYNC16(koff + (r*8 + (c ^ (r & 7)))*16,
                           &Kg[(size_t)(kc + 64 + r) * DM + c*8]);
            }
            CP_COMMIT();
        }

        const unsigned int kb = kbase + buf * (512*16);
        #pragma unroll
        for (int u2 = 0; u2 < 4; u2++) {
            float sacc[2][2][4] = {};
            #pragma unroll
            for (int ks = 0; ks < 4; ks++) {
                unsigned int bf[4];
                int r = u2*16 + (lane & 7) + ((lane >> 4) << 3);
                int c = (ks*2 + ((lane >> 3) & 1)) ^ (r & 7);
                LDMX4(bf[0], bf[1], bf[2], bf[3], kb + (r*8 + c)*16);
                #pragma unroll
                for (int mt = 0; mt < 2; mt++) {
                    MMA16816(sacc[mt][0], qf[mt][ks][0],qf[mt][ks][1],qf[mt][ks][2],qf[mt][ks][3], bf[0], bf[1]);
                    MMA16816(sacc[mt][1], qf[mt][ks][0],qf[mt][ks][1],qf[mt][ks][2],qf[mt][ks][3], bf[2], bf[3]);
                }
            }
            #pragma unroll
            for (int mt = 0; mt < 2; mt++) {
                #pragma unroll
                for (int j = 0; j < 2; j++) {
                    rsum[mt][0] += __expf(sacc[mt][j][0]) + __expf(sacc[mt][j][1]);
                    rsum[mt][1] += __expf(sacc[mt][j][2]) + __expf(sacc[mt][j][3]);
                }
            }
        }
        __syncthreads();
    }

    // quad reduce: all 4 lanes of a row group end with the full sum
    float inv[2][2];
    #pragma unroll
    for (int mt = 0; mt < 2; mt++) {
        #pragma unroll
        for (int hh = 0; hh < 2; hh++) {
            float s = rsum[mt][hh];
            s += __shfl_xor_sync(0xffffffffu, s, 1);
            s += __shfl_xor_sync(0xffffffffu, s, 2);
            inv[mt][hh] = 1.0f / s;
        }
    }

    // ---------------- Phase 2: P + O ----------------
    // prologue: cp.async K,V chunk 0 (all warps past phase-1 reads)
    #pragma unroll
    for (int ci = tid; ci < 512; ci += 128) {
        int r = ci >> 3, c = ci & 7;
        unsigned int off = (r*8 + (c ^ (r & 7)))*16;
        CP_ASYNC16(kbase + off, &Kg[(size_t)r * DM + c*8]);
        CP_ASYNC16(vbase + off, &Vg[(size_t)r * DM + c*8]);
    }
    CP_COMMIT();

    const int lrow = lane >> 2;
    const int cl2 = (lane & 3) * 2;

    float oacc[2][8][4] = {};

    for (int kc = 0; kc < LL; kc += 64) {
        const int buf = (kc >> 6) & 1;
        CP_WAIT0();
        __syncthreads();
        if (kc + 64 < LL) {
            const unsigned int koff = kbase + (buf ^ 1) * (512*16);
            const unsigned int voff = vbase + (buf ^ 1) * (512*16);
            #pragma unroll
            for (int ci = tid; ci < 512; ci += 128) {
                int r = ci >> 3, c = ci & 7;
                unsigned int off = (r*8 + (c ^ (r & 7)))*16;
                CP_ASYNC16(koff + off, &Kg[(size_t)(kc + 64 + r) * DM + c*8]);
                CP_ASYNC16(voff + off, &Vg[(size_t)(kc + 64 + r) * DM + c*8]);
            }
            CP_COMMIT();
        }

        const unsigned int kb = kbase + buf * (512*16);
        unsigned int afr[2][4][4];
        #pragma unroll
        for (int u2 = 0; u2 < 4; u2++) {
            float sacc[2][2][4] = {};
            #pragma unroll
            for (int ks = 0; ks < 4; ks++) {
                unsigned int bf[4];
                int r = u2*16 + (lane & 7) + ((lane >> 4) << 3);
                int c = (ks*2 + ((lane >> 3) & 1)) ^ (r & 7);
                LDMX4(bf[0], bf[1], bf[2], bf[3], kb + (r*8 + c)*16);
                #pragma unroll
                for (int mt = 0; mt < 2; mt++) {
                    MMA16816(sacc[mt][0], qf[mt][ks][0],qf[mt][ks][1],qf[mt][ks][2],qf[mt][ks][3], bf[0], bf[1]);
                    MMA16816(sacc[mt][1], qf[mt][ks][0],qf[mt][ks][1],qf[mt][ks][2],qf[mt][ks][3], bf[2], bf[3]);
                }
            }
            #pragma unroll
            for (int mt = 0; mt < 2; mt++) {
                #pragma unroll
                for (int j = 0; j < 2; j++) {
                    float2 p0, p1;
                    p0.x = __expf(sacc[mt][j][0]) * inv[mt][0];
                    p0.y = __expf(sacc[mt][j][1]) * inv[mt][0];
                    p1.x = __expf(sacc[mt][j][2]) * inv[mt][1];
                    p1.y = __expf(sacc[mt][j][3]) * inv[mt][1];
                    int rowa = bm + wm + mt*16 + lrow;
                    int col  = kc + u2*16 + j*8 + cl2;
                    *(float2*)&P[(size_t)rowa * LL + col]       = p0;
                    *(float2*)&P[(size_t)(rowa + 8) * LL + col] = p1;
                    __half2 h0 = __floats2half2_rn(p0.x, p0.y);
                    __half2 h1 = __floats2half2_rn(p1.x, p1.y);
                    afr[mt][u2][j*2 + 0] = *(unsigned int*)&h0;
                    afr[mt][u2][j*2 + 1] = *(unsigned int*)&h1;
                }
            }
        }

        const unsigned int vb = vbase + buf * (512*16);
        #pragma unroll
        for (int kk = 0; kk < 4; kk++) {
            #pragma unroll
            for (int u2 = 0; u2 < 4; u2++) {
                unsigned int bf[4];
                int r = kk*16 + (lane & 7) + (((lane >> 3) & 1) << 3);
                int c = (u2*2 + ((lane >> 4) & 1)) ^ (r & 7);
                LDMX4T(bf[0], bf[1], bf[2], bf[3], vb + (r*8 + c)*16);
                #pragma unroll
                for (int mt = 0; mt < 2; mt++) {
                    MMA16816(oacc[mt][u2*2],   afr[mt][kk][0],afr[mt][kk][1],afr[mt][kk][2],afr[mt][kk][3], bf[0], bf[1]);
                    MMA16816(oacc[mt][u2*2+1], afr[mt][kk][0],afr[mt][kk][1],afr[mt][kk][2],afr[mt][kk][3], bf[2], bf[3]);
                }
            }
        }
        __syncthreads();
    }

    #pragma unroll
    for (int mt = 0; mt < 2; mt++) {
        #pragma unroll
        for (int u = 0; u < 8; u++) {
            #pragma unroll
            for (int hh = 0; hh < 2; hh++) {
                int r = bm + wm + mt*16 + lrow + hh*8;
                float2 v = make_float2(oacc[mt][u][hh*2], oacc[mt][u][hh*2+1]);
                *(float2*)&out[(size_t)(b * LL + r) * DM + h * DK + u*8 + cl2] = v;
            }
        }
    }
}

// ---------------------------------------------------------------------------
extern "C" void kernel_launch(void* const* d_in, const int* in_sizes, int n_in,
                              void* d_out, int out_size)
{
    const float* q  = (const float*)d_in[0];
    const float* k  = (const float*)d_in[1];
    const float* v  = (const float*)d_in[2];
    const float* Wq = (const float*)d_in[3];
    const float* bq = (const float*)d_in[4];
    const float* Wk = (const float*)d_in[5];
    const float* bk = (const float*)d_in[6];
    const float* Wv = (const float*)d_in[7];
    const float* bv = (const float*)d_in[8];

    float* out  = (float*)d_out;
    float* attn = out + OUT_ELEMS;

    __half *gQ, *gK, *gV;
    cudaGetSymbolAddress((void**)&gQ, g_Qh);
    cudaGetSymbolAddress((void**)&gK, g_Kh);
    cudaGetSymbolAddress((void**)&gV, g_Vh);

    ProjArgs pa;
    pa.X[0] = q;  pa.X[1] = k;  pa.X[2] = v;
    pa.W[0] = Wq; pa.W[1] = Wk; pa.W[2] = Wv;
    pa.b[0] = bq; pa.b[1] = bk; pa.b[2] = bv;
    pa.Y[0] = gQ; pa.Y[1] = gK; pa.Y[2] = gV;
    pa.scale[0] = 0.125f; pa.scale[1] = 1.0f; pa.scale[2] = 1.0f;

    proj_tc_kernel<<<dim3(4, 64, 3), dim3(256)>>>(pa);
    attn_fused_kernel<<<dim3(16, 32), dim3(128)>>>(attn, out);
}